// round 10
// baseline (speedup 1.0000x reference)
#include <cuda_runtime.h>
#include <math.h>

// Problem constants (fixed by setup_inputs)
#define M 16384
#define P 512
#define K 10
#define NMAT 11          // 10 class matrices + 1 global
#define EPSV 0.01f
#define T_BLK 16         // blocks per matrix in fused Cholesky

// ---------------- device scratch (no allocs allowed) ----------------
__device__ __align__(16) float g_A[NMAT * P * P];   // raw grams -> B -> L (lower triangle only)
__device__ int g_idx[M];
__device__ int g_cnt[16];
__device__ int g_off[16];
__device__ int g_cur[16];
__device__ int g_bar[NMAT];     // per-matrix barrier arrival counter
__device__ int g_gen[NMAT];     // per-matrix barrier generation
__device__ int g_done;          // matrices finished
__device__ float g_sums[NMAT];  // per-matrix sum(log diag L)

// ---------------- f32x2 packed FMA helpers (sm_103a) ----------------
__device__ __forceinline__ unsigned long long pack2(float x, float y) {
    unsigned long long r;
    asm("mov.b64 %0, {%1,%2};" : "=l"(r) : "f"(x), "f"(y));
    return r;
}
__device__ __forceinline__ void unpack2(unsigned long long v, float &a, float &b) {
    asm("mov.b64 {%0,%1}, %2;" : "=f"(a), "=f"(b) : "l"(v));
}
__device__ __forceinline__ void ffma2(unsigned long long &d, unsigned long long a, unsigned long long b) {
    asm("fma.rn.f32x2 %0, %1, %2, %0;" : "+l"(d) : "l"(a), "l"(b));
}

// ---------------- zero scratch + barrier state (every launch: replay-deterministic) ----------------
__global__ void zeroA_kernel() {
    int n = K * P * P;   // only class grams need zeroing (atomic targets); matrix 10 fully written by assemble
    for (int i = blockIdx.x * blockDim.x + threadIdx.x; i < n; i += gridDim.x * blockDim.x)
        g_A[i] = 0.f;
    if (blockIdx.x == 0 && threadIdx.x < NMAT + 1) {
        if (threadIdx.x < NMAT) { g_bar[threadIdx.x] = 0; g_gen[threadIdx.x] = 0; }
        else g_done = 0;
    }
}

// ---------------- class histogram + offsets (Y is int32) ----------------
__global__ void hist_kernel(const int* __restrict__ Y) {
    __shared__ int h[K];
    int tid = threadIdx.x;
    if (tid < K) h[tid] = 0;
    __syncthreads();
    for (int i = tid; i < M; i += blockDim.x) {
        int c = Y[i];
        if (c >= 0 && c < K) atomicAdd(&h[c], 1);
    }
    __syncthreads();
    if (tid == 0) {
        int acc = 0;
        for (int c = 0; c < K; c++) {
            g_cnt[c] = h[c];
            g_off[c] = acc;
            g_cur[c] = acc;
            acc += h[c];
        }
    }
}

// ---------------- scatter row indices by class ----------------
__global__ void scatter_kernel(const int* __restrict__ Y) {
    for (int i = blockIdx.x * blockDim.x + threadIdx.x; i < M; i += gridDim.x * blockDim.x) {
        int c = Y[i];
        if (c < 0 || c >= K) continue;
        int pos = atomicAdd(&g_cur[c], 1);
        g_idx[pos] = i;
    }
}

// ---------------- per-class SYRK: lower 128x128 tiles, f32x2 FMAs ----------------
#define CH 16
#define NSPLIT 8

__global__ __launch_bounds__(256) void gram_kernel(const float* __restrict__ X) {
    __shared__ __align__(16) float As[CH][128];
    __shared__ __align__(16) float Bs[CH][128];
    __shared__ int rid[CH];

    const int TI[10] = {0, 1, 1, 2, 2, 2, 3, 3, 3, 3};
    const int TJ[10] = {0, 0, 1, 0, 1, 2, 0, 1, 2, 3};

    int c  = blockIdx.y;
    int ti = TI[blockIdx.x];
    int tj = TJ[blockIdx.x];
    int off = g_off[c], cnt = g_cnt[c];
    int s = blockIdx.z;
    int rbeg = off + (cnt * s) / NSPLIT;
    int rend = off + (cnt * (s + 1)) / NSPLIT;

    int tid = threadIdx.x;
    int tx = tid & 15, ty = tid >> 4;

    unsigned long long acc[8][4];
#pragma unroll
    for (int r = 0; r < 8; r++)
#pragma unroll
        for (int q = 0; q < 4; q++) acc[r][q] = 0ull;

    for (int r0 = rbeg; r0 < rend; r0 += CH) {
        __syncthreads();
        if (tid < CH) rid[tid] = (r0 + tid < rend) ? g_idx[r0 + tid] : -1;
        __syncthreads();
        for (int e = tid; e < CH * 32; e += 256) {
            int rr = e >> 5, f = e & 31;
            int gi = rid[rr];
            float4 va = make_float4(0.f, 0.f, 0.f, 0.f);
            float4 vb = va;
            if (gi >= 0) {
                const float* rp = X + (long long)gi * P;
                va = *(const float4*)(rp + ti * 128 + f * 4);
                vb = *(const float4*)(rp + tj * 128 + f * 4);
            }
            *(float4*)&As[rr][f * 4] = va;
            *(float4*)&Bs[rr][f * 4] = vb;
        }
        __syncthreads();
#pragma unroll
        for (int kk = 0; kk < CH; kk++) {
            float4 a0 = *(const float4*)&As[kk][ty * 8];
            float4 a1 = *(const float4*)&As[kk][ty * 8 + 4];
            ulonglong2 bb0 = *(const ulonglong2*)&Bs[kk][tx * 8];
            ulonglong2 bb1 = *(const ulonglong2*)&Bs[kk][tx * 8 + 4];
            unsigned long long bv[4] = {bb0.x, bb0.y, bb1.x, bb1.y};
            float av[8] = {a0.x, a0.y, a0.z, a0.w, a1.x, a1.y, a1.z, a1.w};
#pragma unroll
            for (int r = 0; r < 8; r++) {
                unsigned long long ar = pack2(av[r], av[r]);
#pragma unroll
                for (int q = 0; q < 4; q++) ffma2(acc[r][q], ar, bv[q]);
            }
        }
    }

    float* Ac = g_A + c * P * P;
    bool dg = (ti == tj);
#pragma unroll
    for (int r = 0; r < 8; r++) {
        int i = ti * 128 + ty * 8 + r;
#pragma unroll
        for (int q = 0; q < 4; q++) {
            float v0, v1;
            unpack2(acc[r][q], v0, v1);
            int j = tj * 128 + tx * 8 + q * 2;
            if (!dg || j <= i)     atomicAdd(&Ac[i * P + j], v0);
            if (!dg || j + 1 <= i) atomicAdd(&Ac[i * P + j + 1], v1);
        }
    }
}

// ---------------- B = I + scal*Gram (lower), B[10] = I + 3.125*sum ----------------
__global__ void assemble_kernel() {
    int e = blockIdx.x * blockDim.x + threadIdx.x;
    if (e >= P * P) return;
    int i = e >> 9, j = e & (P - 1);
    if (j > i) return;
    float add = (i == j) ? 1.f : 0.f;
    float s = 0.f;
#pragma unroll
    for (int c = 0; c < K; c++) {
        float v = g_A[c * P * P + e];
        s += v;
        float trPi = (float)g_cnt[c] + 1e-8f;
        float scal = (float)P / (trPi * EPSV);
        g_A[c * P * P + e] = scal * v + add;
    }
    float scal_g = (float)P / ((float)M * EPSV);   // 3.125
    g_A[K * P * P + e] = scal_g * s + add;
}

// ---------------- per-matrix software barrier (all T_BLK blocks of matrix c) ----------------
__device__ __forceinline__ void mat_barrier(int c) {
    __threadfence();          // publish this thread's writes (gpu scope)
    __syncthreads();
    if (threadIdx.x == 0) {
        int g = atomicAdd(&g_gen[c], 0);
        int a = atomicAdd(&g_bar[c], 1);
        if (a == T_BLK - 1) {
            atomicExch(&g_bar[c], 0);
            __threadfence();
            atomicAdd(&g_gen[c], 1);
        } else {
            while (atomicAdd(&g_gen[c], 0) == g) __nanosleep(64);
        }
    }
    __syncthreads();
    __threadfence();          // acquire: invalidate stale L1 before post-barrier reads
}

// ---------------- fused Cholesky: 8x(factor | distributed TRSM | SYRK) + logdet ----------------
__global__ __launch_bounds__(256, 2) void chol_kernel(float* __restrict__ out) {
    __shared__ float sA[64 * 65];
    __shared__ float sB[64 * 65];
    __shared__ float sInv[64];
    __shared__ float red[256];

    int c = blockIdx.y;
    int b = blockIdx.x;
    int tid = threadIdx.x;
    float* A = g_A + c * P * P;

    for (int k = 0; k < 8; k++) {
        int kb = k * 64;

        // ---- phase 1: block 0 factors the 64x64 diagonal tile ----
        if (b == 0) {
            for (int e = tid; e < 4096; e += 256) {
                int i = e >> 6, j = e & 63;
                sA[i * 65 + j] = (j <= i) ? A[(kb + i) * P + kb + j] : 0.f;
            }
            for (int j = 0; j < 64; j++) {
                __syncthreads();
                float invd = 1.0f / sA[j * 65 + j];
                for (int i = j + 1 + (tid >> 4); i < 64; i += 16) {
                    float cij = sA[i * 65 + j] * invd;
                    for (int t = j + 1 + (tid & 15); t <= i; t += 16)
                        sA[i * 65 + t] -= cij * sA[t * 65 + j];
                }
            }
            __syncthreads();
            if (tid < 64) sInv[tid] = rsqrtf(sA[tid * 65 + tid]);
            __syncthreads();
            for (int e = tid; e < 4096; e += 256) {
                int i = e >> 6, j = e & 63;
                if (j <= i) {
                    float v = sA[i * 65 + j] * sInv[j];
                    sA[i * 65 + j] = v;
                    A[(kb + i) * P + kb + j] = v;
                }
            }
        }
        mat_barrier(c);

        // ---- phase 2: distributed TRSM (all blocks; rows strided) ----
        int rows = P - kb - 64;
        if (rows > 0) {
            // every block loads the L tile (L2-resident) + inv diag
            for (int e = tid; e < 4096; e += 256) {
                int i = e >> 6, j = e & 63;
                sA[i * 65 + j] = (j <= i) ? A[(kb + i) * P + kb + j] : 0.f;
            }
            __syncthreads();
            if (tid < 64) sInv[tid] = 1.0f / sA[tid * 65 + tid];
            __syncthreads();
            int rl = b + T_BLK * tid;
            if (rl < rows) {
                int row = kb + 64 + rl;
                float w[64];
                const float* rp = A + row * P + kb;
#pragma unroll
                for (int q = 0; q < 16; q++) {
                    float4 v = *(const float4*)(rp + q * 4);
                    w[4 * q] = v.x; w[4 * q + 1] = v.y; w[4 * q + 2] = v.z; w[4 * q + 3] = v.w;
                }
#pragma unroll
                for (int j = 0; j < 64; j++) {
                    float xj = w[j] * sInv[j];
                    w[j] = xj;
#pragma unroll
                    for (int t = j + 1; t < 64; t++) w[t] -= xj * sA[t * 65 + j];
                }
                float* wp = A + row * P + kb;
#pragma unroll
                for (int q = 0; q < 16; q++)
                    *(float4*)(wp + q * 4) = make_float4(w[4 * q], w[4 * q + 1], w[4 * q + 2], w[4 * q + 3]);
            }
        }
        mat_barrier(c);

        // ---- phase 3: trailing SYRK update (tiles round-robin; block 0 last) ----
        int nt = 7 - k;
        int tiles = nt * (nt + 1) / 2;
        int bb = (b + T_BLK - 1) % T_BLK;   // block0 -> slot 15 (panel block gets least syrk work)
        for (int l = bb; l < tiles; l += T_BLK) {
            int bi = 0, ll = l;
            while (ll >= bi + 1) { ll -= bi + 1; bi++; }
            int bj = ll;
            int I = kb + 64 + bi * 64;
            int J = kb + 64 + bj * 64;

            __syncthreads();
            for (int e = tid; e < 4096; e += 256) {
                int r = e >> 6, t = e & 63;
                sA[t * 65 + r] = A[(I + r) * P + kb + t];
                sB[t * 65 + r] = A[(J + r) * P + kb + t];
            }
            __syncthreads();

            int tx = tid & 15, ty = tid >> 4;
            float acc[4][4];
#pragma unroll
            for (int r = 0; r < 4; r++)
#pragma unroll
                for (int s = 0; s < 4; s++) acc[r][s] = 0.f;
#pragma unroll 4
            for (int t = 0; t < 64; t++) {
                float a[4], bv[4];
#pragma unroll
                for (int r = 0; r < 4; r++) a[r] = sA[t * 65 + ty * 4 + r];
#pragma unroll
                for (int s = 0; s < 4; s++) bv[s] = sB[t * 65 + tx * 4 + s];
#pragma unroll
                for (int r = 0; r < 4; r++)
#pragma unroll
                    for (int s = 0; s < 4; s++) acc[r][s] += a[r] * bv[s];
            }
            bool dg = (bi == bj);
#pragma unroll
            for (int r = 0; r < 4; r++) {
                int li = ty * 4 + r;
#pragma unroll
                for (int s = 0; s < 4; s++) {
                    int lj = tx * 4 + s;
                    if (!dg || lj <= li)
                        A[(I + li) * P + J + lj] -= acc[r][s];
                }
            }
        }
        mat_barrier(c);
    }

    // ---- final: block 0 of each matrix reduces log diag; last matrix writes out ----
    if (b == 0) {
        float s = 0.f;
        for (int i = tid; i < P; i += 256) s += logf(A[i * P + i]);
        red[tid] = s;
        __syncthreads();
        for (int st = 128; st > 0; st >>= 1) {
            if (tid < st) red[tid] += red[tid + st];
            __syncthreads();
        }
        if (tid == 0) {
            g_sums[c] = red[0];
            __threadfence();
            int old = atomicAdd(&g_done, 1);
            if (old == NMAT - 1) {
                __threadfence();
                float comp = 0.f;
                for (int cc = 0; cc < K; cc++) {
                    float trPi = (float)g_cnt[cc] + 1e-8f;
                    comp += g_sums[cc] * trPi / (float)M;
                }
                out[0] = g_sums[K];   // discrimn = sum(log diag L) = logdet/2
                out[1] = comp;
            }
        }
    }
}

// ---------------- launch ----------------
extern "C" void kernel_launch(void* const* d_in, const int* in_sizes, int n_in,
                              void* d_out, int out_size) {
    const float* X = (const float*)d_in[0];
    const int* Y = (const int*)d_in[1];   // int32: JAX demotes int64 without x64 mode
    float* out = (float*)d_out;

    zeroA_kernel<<<2048, 256>>>();
    hist_kernel<<<1, 256>>>(Y);
    scatter_kernel<<<64, 256>>>(Y);
    gram_kernel<<<dim3(10, K, NSPLIT), 256>>>(X);
    assemble_kernel<<<(P * P + 255) / 256, 256>>>();
    chol_kernel<<<dim3(T_BLK, NMAT), 256>>>(out);
}

// round 12
// speedup vs baseline: 1.0646x; 1.0646x over previous
#include <cuda_runtime.h>
#include <math.h>

// Problem constants (fixed by setup_inputs)
#define M 16384
#define P 512
#define K 10
#define NMAT 11          // 10 class matrices + 1 global
#define EPSV 0.01f
#define CB 8             // cluster CTAs per matrix (hardware cluster barrier)

// ---------------- device scratch (no allocs allowed) ----------------
__device__ __align__(16) float g_A[NMAT * P * P];   // raw grams -> B -> L (lower triangle only)
__device__ int g_idx[M];
__device__ int g_cnt[16];
__device__ int g_off[16];
__device__ int g_cur[16];
__device__ int g_done;          // matrices finished
__device__ float g_sums[NMAT];  // per-matrix sum(log diag L)

// ---------------- cluster barrier ----------------
__device__ __forceinline__ void cluster_sync() {
    asm volatile("barrier.cluster.arrive.aligned;" ::: "memory");
    asm volatile("barrier.cluster.wait.aligned;" ::: "memory");
}

// ---------------- f32x2 packed FMA helpers (sm_103a) ----------------
__device__ __forceinline__ unsigned long long pack2(float x, float y) {
    unsigned long long r;
    asm("mov.b64 %0, {%1,%2};" : "=l"(r) : "f"(x), "f"(y));
    return r;
}
__device__ __forceinline__ void unpack2(unsigned long long v, float &a, float &b) {
    asm("mov.b64 {%0,%1}, %2;" : "=f"(a), "=f"(b) : "l"(v));
}
__device__ __forceinline__ void ffma2(unsigned long long &d, unsigned long long a, unsigned long long b) {
    asm("fma.rn.f32x2 %0, %1, %2, %0;" : "+l"(d) : "l"(a), "l"(b));
}

// ---------------- zero scratch + flags (every launch: replay-deterministic) ----------------
__global__ void zeroA_kernel() {
    int n = K * P * P;   // only class grams need zeroing (atomic targets); matrix 10 fully written by assemble
    for (int i = blockIdx.x * blockDim.x + threadIdx.x; i < n; i += gridDim.x * blockDim.x)
        g_A[i] = 0.f;
    if (blockIdx.x == 0 && threadIdx.x == 0) g_done = 0;
}

// ---------------- class histogram + offsets (Y is int32) ----------------
__global__ void hist_kernel(const int* __restrict__ Y) {
    __shared__ int h[K];
    int tid = threadIdx.x;
    if (tid < K) h[tid] = 0;
    __syncthreads();
    for (int i = tid; i < M; i += blockDim.x) {
        int c = Y[i];
        if (c >= 0 && c < K) atomicAdd(&h[c], 1);
    }
    __syncthreads();
    if (tid == 0) {
        int acc = 0;
        for (int c = 0; c < K; c++) {
            g_cnt[c] = h[c];
            g_off[c] = acc;
            g_cur[c] = acc;
            acc += h[c];
        }
    }
}

// ---------------- scatter row indices by class ----------------
__global__ void scatter_kernel(const int* __restrict__ Y) {
    for (int i = blockIdx.x * blockDim.x + threadIdx.x; i < M; i += gridDim.x * blockDim.x) {
        int c = Y[i];
        if (c < 0 || c >= K) continue;
        int pos = atomicAdd(&g_cur[c], 1);
        g_idx[pos] = i;
    }
}

// ---------------- per-class SYRK: lower 128x128 tiles, f32x2 FMAs ----------------
#define CH 16
#define NSPLIT 8

__global__ __launch_bounds__(256) void gram_kernel(const float* __restrict__ X) {
    __shared__ __align__(16) float As[CH][128];
    __shared__ __align__(16) float Bs[CH][128];
    __shared__ int rid[CH];

    const int TI[10] = {0, 1, 1, 2, 2, 2, 3, 3, 3, 3};
    const int TJ[10] = {0, 0, 1, 0, 1, 2, 0, 1, 2, 3};

    int c  = blockIdx.y;
    int ti = TI[blockIdx.x];
    int tj = TJ[blockIdx.x];
    int off = g_off[c], cnt = g_cnt[c];
    int s = blockIdx.z;
    int rbeg = off + (cnt * s) / NSPLIT;
    int rend = off + (cnt * (s + 1)) / NSPLIT;

    int tid = threadIdx.x;
    int tx = tid & 15, ty = tid >> 4;

    unsigned long long acc[8][4];
#pragma unroll
    for (int r = 0; r < 8; r++)
#pragma unroll
        for (int q = 0; q < 4; q++) acc[r][q] = 0ull;

    for (int r0 = rbeg; r0 < rend; r0 += CH) {
        __syncthreads();
        if (tid < CH) rid[tid] = (r0 + tid < rend) ? g_idx[r0 + tid] : -1;
        __syncthreads();
        for (int e = tid; e < CH * 32; e += 256) {
            int rr = e >> 5, f = e & 31;
            int gi = rid[rr];
            float4 va = make_float4(0.f, 0.f, 0.f, 0.f);
            float4 vb = va;
            if (gi >= 0) {
                const float* rp = X + (long long)gi * P;
                va = *(const float4*)(rp + ti * 128 + f * 4);
                vb = *(const float4*)(rp + tj * 128 + f * 4);
            }
            *(float4*)&As[rr][f * 4] = va;
            *(float4*)&Bs[rr][f * 4] = vb;
        }
        __syncthreads();
#pragma unroll
        for (int kk = 0; kk < CH; kk++) {
            float4 a0 = *(const float4*)&As[kk][ty * 8];
            float4 a1 = *(const float4*)&As[kk][ty * 8 + 4];
            ulonglong2 bb0 = *(const ulonglong2*)&Bs[kk][tx * 8];
            ulonglong2 bb1 = *(const ulonglong2*)&Bs[kk][tx * 8 + 4];
            unsigned long long bv[4] = {bb0.x, bb0.y, bb1.x, bb1.y};
            float av[8] = {a0.x, a0.y, a0.z, a0.w, a1.x, a1.y, a1.z, a1.w};
#pragma unroll
            for (int r = 0; r < 8; r++) {
                unsigned long long ar = pack2(av[r], av[r]);
#pragma unroll
                for (int q = 0; q < 4; q++) ffma2(acc[r][q], ar, bv[q]);
            }
        }
    }

    float* Ac = g_A + c * P * P;
    bool dg = (ti == tj);
#pragma unroll
    for (int r = 0; r < 8; r++) {
        int i = ti * 128 + ty * 8 + r;
#pragma unroll
        for (int q = 0; q < 4; q++) {
            float v0, v1;
            unpack2(acc[r][q], v0, v1);
            int j = tj * 128 + tx * 8 + q * 2;
            if (!dg || j <= i)     atomicAdd(&Ac[i * P + j], v0);
            if (!dg || j + 1 <= i) atomicAdd(&Ac[i * P + j + 1], v1);
        }
    }
}

// ---------------- B = I + scal*Gram (lower), B[10] = I + 3.125*sum ----------------
__global__ void assemble_kernel() {
    int e = blockIdx.x * blockDim.x + threadIdx.x;
    if (e >= P * P) return;
    int i = e >> 9, j = e & (P - 1);
    if (j > i) return;
    float add = (i == j) ? 1.f : 0.f;
    float s = 0.f;
#pragma unroll
    for (int c = 0; c < K; c++) {
        float v = g_A[c * P * P + e];
        s += v;
        float trPi = (float)g_cnt[c] + 1e-8f;
        float scal = (float)P / (trPi * EPSV);
        g_A[c * P * P + e] = scal * v + add;
    }
    float scal_g = (float)P / ((float)M * EPSV);   // 3.125
    g_A[K * P * P + e] = scal_g * s + add;
}

// ---------------- fused Cholesky: one 8-CTA cluster per matrix ----------------
// Per k-step: CTA0 factors 64x64 diag tile | cluster.sync | all CTAs TRSM (rows
// strided over cluster) | cluster.sync | SYRK tiles round-robin | cluster.sync.
// Cluster barrier = HW arrive/wait (~0.3us) with cluster-scope acq/rel + L1 inval.
__global__ __launch_bounds__(256, 2) __cluster_dims__(CB, 1, 1)
void chol_kernel(float* __restrict__ out) {
    __shared__ float sA[64 * 65];
    __shared__ float sB[64 * 65];
    __shared__ float sInv[64];
    __shared__ float red[256];

    int c = blockIdx.y;
    int b = blockIdx.x;          // rank within cluster (cluster dims = (CB,1,1))
    int tid = threadIdx.x;
    float* A = g_A + c * P * P;

    for (int k = 0; k < 8; k++) {
        int kb = k * 64;

        // ---- phase 1: CTA0 factors the 64x64 diagonal tile ----
        if (b == 0) {
            for (int e = tid; e < 4096; e += 256) {
                int i = e >> 6, j = e & 63;
                sA[i * 65 + j] = (j <= i) ? A[(kb + i) * P + kb + j] : 0.f;
            }
            for (int j = 0; j < 64; j++) {
                __syncthreads();
                float invd = 1.0f / sA[j * 65 + j];
                for (int i = j + 1 + (tid >> 4); i < 64; i += 16) {
                    float cij = sA[i * 65 + j] * invd;
                    for (int t = j + 1 + (tid & 15); t <= i; t += 16)
                        sA[i * 65 + t] -= cij * sA[t * 65 + j];
                }
            }
            __syncthreads();
            if (tid < 64) sInv[tid] = rsqrtf(sA[tid * 65 + tid]);
            __syncthreads();
            for (int e = tid; e < 4096; e += 256) {
                int i = e >> 6, j = e & 63;
                if (j <= i) {
                    float v = sA[i * 65 + j] * sInv[j];
                    A[(kb + i) * P + kb + j] = v;
                }
            }
        }
        cluster_sync();

        // ---- phase 2: TRSM, rows strided across the 8 cluster CTAs ----
        int rows = P - kb - 64;
        if (rows > 0) {
            for (int e = tid; e < 4096; e += 256) {
                int i = e >> 6, j = e & 63;
                sA[i * 65 + j] = (j <= i) ? A[(kb + i) * P + kb + j] : 0.f;
            }
            __syncthreads();
            if (tid < 64) sInv[tid] = 1.0f / sA[tid * 65 + tid];
            __syncthreads();
            int rl = b + CB * tid;
            if (rl < rows) {
                int row = kb + 64 + rl;
                float w[64];
                const float* rp = A + row * P + kb;
#pragma unroll
                for (int q = 0; q < 16; q++) {
                    float4 v = *(const float4*)(rp + q * 4);
                    w[4 * q] = v.x; w[4 * q + 1] = v.y; w[4 * q + 2] = v.z; w[4 * q + 3] = v.w;
                }
#pragma unroll
                for (int j = 0; j < 64; j++) {
                    float xj = w[j] * sInv[j];
                    w[j] = xj;
#pragma unroll
                    for (int t = j + 1; t < 64; t++) w[t] -= xj * sA[t * 65 + j];
                }
                float* wp = A + row * P + kb;
#pragma unroll
                for (int q = 0; q < 16; q++)
                    *(float4*)(wp + q * 4) = make_float4(w[4 * q], w[4 * q + 1], w[4 * q + 2], w[4 * q + 3]);
            }
        }
        cluster_sync();

        // ---- phase 3: trailing SYRK update (tiles round-robin; CTA0 least) ----
        int nt = 7 - k;
        int tiles = nt * (nt + 1) / 2;
        int bb = (b + CB - 1) % CB;
        for (int l = bb; l < tiles; l += CB) {
            int bi = 0, ll = l;
            while (ll >= bi + 1) { ll -= bi + 1; bi++; }
            int bj = ll;
            int I = kb + 64 + bi * 64;
            int J = kb + 64 + bj * 64;

            __syncthreads();
            for (int e = tid; e < 4096; e += 256) {
                int r = e >> 6, t = e & 63;
                sA[t * 65 + r] = A[(I + r) * P + kb + t];
                sB[t * 65 + r] = A[(J + r) * P + kb + t];
            }
            __syncthreads();

            int tx = tid & 15, ty = tid >> 4;
            float acc[4][4];
#pragma unroll
            for (int r = 0; r < 4; r++)
#pragma unroll
                for (int s = 0; s < 4; s++) acc[r][s] = 0.f;
#pragma unroll 4
            for (int t = 0; t < 64; t++) {
                float a[4], bv[4];
#pragma unroll
                for (int r = 0; r < 4; r++) a[r] = sA[t * 65 + ty * 4 + r];
#pragma unroll
                for (int s = 0; s < 4; s++) bv[s] = sB[t * 65 + tx * 4 + s];
#pragma unroll
                for (int r = 0; r < 4; r++)
#pragma unroll
                    for (int s = 0; s < 4; s++) acc[r][s] += a[r] * bv[s];
            }
            bool dg = (bi == bj);
#pragma unroll
            for (int r = 0; r < 4; r++) {
                int li = ty * 4 + r;
#pragma unroll
                for (int s = 0; s < 4; s++) {
                    int lj = tx * 4 + s;
                    if (!dg || lj <= li)
                        A[(I + li) * P + J + lj] -= acc[r][s];
                }
            }
        }
        cluster_sync();
    }

    // ---- final: CTA0 of each cluster reduces log diag; last matrix writes out ----
    if (b == 0) {
        float s = 0.f;
        for (int i = tid; i < P; i += 256) s += logf(A[i * P + i]);
        red[tid] = s;
        __syncthreads();
        for (int st = 128; st > 0; st >>= 1) {
            if (tid < st) red[tid] += red[tid + st];
            __syncthreads();
        }
        if (tid == 0) {
            g_sums[c] = red[0];
            __threadfence();   // cross-cluster publish (gpu scope)
            int old = atomicAdd(&g_done, 1);
            if (old == NMAT - 1) {
                __threadfence();
                float comp = 0.f;
                for (int cc = 0; cc < K; cc++) {
                    float trPi = (float)g_cnt[cc] + 1e-8f;
                    comp += g_sums[cc] * trPi / (float)M;
                }
                out[0] = g_sums[K];   // discrimn = sum(log diag L) = logdet/2
                out[1] = comp;
            }
        }
    }
}

// ---------------- launch ----------------
extern "C" void kernel_launch(void* const* d_in, const int* in_sizes, int n_in,
                              void* d_out, int out_size) {
    const float* X = (const float*)d_in[0];
    const int* Y = (const int*)d_in[1];   // int32: JAX demotes int64 without x64 mode
    float* out = (float*)d_out;

    zeroA_kernel<<<2048, 256>>>();
    hist_kernel<<<1, 256>>>(Y);
    scatter_kernel<<<64, 256>>>(Y);
    gram_kernel<<<dim3(10, K, NSPLIT), 256>>>(X);
    assemble_kernel<<<(P * P + 255) / 256, 256>>>();
    chol_kernel<<<dim3(CB, NMAT), 256>>>(out);   // cluster (8,1,1) per matrix
}